// round 3
// baseline (speedup 1.0000x reference)
#include <cuda_runtime.h>
#include <math.h>

// E3nnForce fused kernel, round 2.
//  * Pruned graph: only nodes {1,4,3,5} and edges (1->4),(4->3),(4->5) are live.
//  * Phase B (radial 64->250 GEMM) is CTA-cooperative: Wr2 read once per CTA
//    straight from global; outputs for all 8 triplets in one pass.
//  * f32x2 packed FMA everywhere in the hot GEMM loops.
//  * s/hC state and v/vC state live in single in-place arrays -> smem 107KB,
//    2 CTAs/SM.

#define CC 50
#define TRIPS 8
#define NBLK 4096
#define NTHR 512

typedef unsigned long long ull;

// ---- block-level smem layout (floats) ----
#define WR1S  0            // 12 x 64
#define BR1S  768          // 64
#define WSS   832          // 50 x 50
#define WGS   3332
#define WVS   5832
#define HID2  8336         // [trip][j][8] : {e0,e0,e1,e1,e2,e2,pad,pad}
#define WALL  12432        // [24][252]    : radial weights per (trip,edge)
#define FCUTD 18480        // [8][3][2]    : {fc,fc}
#define TST   18528        // per-trip regions
#define TSF   1104
#define SMEM_FLOATS (TST + TRIPS * TSF)     // 27360
#define SMEM_BYTES  (SMEM_FLOATS * 4)       // 109440

// ---- per-trip layout (floats, relative) ----
#define OF_S4   0     // float4[50]: (s1, s4, s3, s5)  (doubles as hC)
#define OF_HG   200   // float4[50]: (h4, h3, h5, 0)   (gate-GEMM operand)
#define OF_VC   400   // [50][12]: v4x v4y v4z v3x | v3y v3z v5x v5y | v5z 0 0 0
#define OF_U    1008  // u[3][4]
#define OF_EMB  1020  // emb[3][12]
#define OF_Y2   1056  // Y2[3][9]
#define OF_OFF  1084  // off1 x,y
#define OF_OUTS 1088  // epilogue scratch[6]

__device__ __forceinline__ float sigm_f(float x) { return 1.0f / (1.0f + __expf(-x)); }
__device__ __forceinline__ float silu_f(float x) { return x / (1.0f + __expf(-x)); }

__device__ __forceinline__ ull fma2(ull a, ull b, ull c) {
    ull d;
    asm("fma.rn.f32x2 %0, %1, %2, %3;" : "=l"(d) : "l"(a), "l"(b), "l"(c));
    return d;
}
__device__ __forceinline__ ull mul2(ull a, ull b) {
    ull d;
    asm("mul.rn.f32x2 %0, %1, %2;" : "=l"(d) : "l"(a), "l"(b));
    return d;
}
__device__ __forceinline__ ull pack2(float lo, float hi) {
    ull d;
    asm("mov.b64 %0, {%1, %2};" : "=l"(d) : "f"(lo), "f"(hi));
    return d;
}
__device__ __forceinline__ void unpack2(ull v, float& lo, float& hi) {
    asm("mov.b64 {%0, %1}, %2;" : "=f"(lo), "=f"(hi) : "l"(v));
}

__global__ void __launch_bounds__(NTHR, 2)
e3nn_kernel(const float* __restrict__ y,
            const float* __restrict__ Wemb,
            const float* __restrict__ Wr1g,
            const float* __restrict__ br1g,
            const float* __restrict__ Wr2g,
            const float* __restrict__ Wsg,
            const float* __restrict__ Wvg,
            const float* __restrict__ Wgg,
            const float* __restrict__ Woutg,
            float* __restrict__ outp)
{
    extern __shared__ float sm[];
    const int tid  = threadIdx.x;
    const int trip = tid >> 6;
    const int k    = tid & 63;
    float* ts = sm + TST + trip * TSF;

    const int t = blockIdx.x * TRIPS + trip;
    const int b = t >> 9;
    const int i = t & 511;

    // ---------------- geometry ----------------
    float* scratch = sm + WALL + trip * 16;     // WALL is free pre-loop
    if (k < 3) {
        const float* yy = y + ((size_t)(b * 514 + i + k)) * 6;
        float cx = yy[0], cy = yy[1], a = yy[2];
        float ox = -0.05f * sinf(a), oy = 0.05f * cosf(a);
        scratch[k * 4 + 0] = cx; scratch[k * 4 + 1] = cy;
        scratch[k * 4 + 2] = ox; scratch[k * 4 + 3] = oy;
        if (k == 1) { ts[OF_OFF] = ox; ts[OF_OFF + 1] = oy; }
    }
    __syncthreads();
    if (k < 3) {
        float vx, vy, a0, a1;
        if (k == 0)      { vx = scratch[0] - scratch[4]; vy = scratch[1] - scratch[5]; a0 = 1.f; a1 = 0.f; } // 1->4
        else if (k == 1) { vx = -scratch[6];             vy = -scratch[7];             a0 = 0.f; a1 = 1.f; } // 4->3
        else             { vx =  scratch[6];             vy =  scratch[7];             a0 = 0.f; a1 = 1.f; } // 4->5
        float r   = sqrtf(vx * vx + vy * vy);
        float inv = 1.0f / (r + 1e-12f);
        float ux = vx * inv, uy = vy * inv;
        ts[OF_U + k * 4 + 0] = ux; ts[OF_U + k * 4 + 1] = uy; ts[OF_U + k * 4 + 2] = 0.f;
        float tt = fminf(r * (1.0f / 0.06f), 1.0f);
        float fc = 0.5f * (cosf(3.14159265358979323846f * tt) + 1.0f);
        *(ull*)(sm + FCUTD + (trip * 3 + k) * 2) = pack2(fc, fc);
        #pragma unroll
        for (int ib = 0; ib < 10; ib++) {
            float z = r * 150.0f - (float)ib;
            ts[OF_EMB + k * 12 + ib] = __expf(-z * z) * fc;
        }
        ts[OF_EMB + k * 12 + 10] = a0;
        ts[OF_EMB + k * 12 + 11] = a1;
        float u3[3] = {ux, uy, 0.f};
        #pragma unroll
        for (int rr = 0; rr < 3; rr++)
            #pragma unroll
            for (int cc2 = 0; cc2 < 3; cc2++)
                ts[OF_Y2 + k * 9 + rr * 3 + cc2] = u3[rr] * u3[cc2] - (rr == cc2 ? (1.0f / 3.0f) : 0.0f);
    }
    if (k < CC) {
        float e0 = Wemb[k], e1 = Wemb[50 + k], e2 = Wemb[100 + k];
        *(float4*)(ts + OF_S4 + k * 4) = make_float4(e0 + e1, e0 + e1, e0 + e2, e0 + e2);
        float4 z4 = make_float4(0.f, 0.f, 0.f, 0.f);
        *(float4*)(ts + OF_VC + k * 12 + 0) = z4;
        *(float4*)(ts + OF_VC + k * 12 + 4) = z4;
        *(float4*)(ts + OF_VC + k * 12 + 8) = z4;
    }

    // ---------------- layers ----------------
    for (int l = 0; l < 6; l++) {
        __syncthreads();
        // ---- stage node weights + radial-MLP-1 ----
        {
            const float4* wsg4 = (const float4*)(Wsg + (size_t)l * 2500);
            const float4* wgg4 = (const float4*)(Wgg + (size_t)l * 2500);
            const float4* wvg4 = (const float4*)(Wvg + (size_t)l * 2500);
            float4* wss4 = (float4*)(sm + WSS);
            float4* wgs4 = (float4*)(sm + WGS);
            float4* wvs4 = (float4*)(sm + WVS);
            for (int idx = tid; idx < 625; idx += NTHR) {
                wss4[idx] = wsg4[idx];
                wgs4[idx] = wgg4[idx];
                wvs4[idx] = wvg4[idx];
            }
            if (tid < 192) ((float4*)(sm + WR1S))[tid] = ((const float4*)(Wr1g + (size_t)l * 768))[tid];
            else if (tid < 208) ((float4*)(sm + BR1S))[tid - 192] = ((const float4*)(br1g + (size_t)l * 64))[tid - 192];
        }
        __syncthreads();

        // ---- phase A: hidden = silu(emb @ Wr1 + br1), duplicated pairs ----
        {
            float acc0 = sm[BR1S + k], acc1 = acc0, acc2 = acc0;
            const float* emb = ts + OF_EMB;
            #pragma unroll
            for (int ii = 0; ii < 12; ii++) {
                float wv_ = sm[WR1S + ii * 64 + k];
                acc0 += emb[ii]      * wv_;
                acc1 += emb[12 + ii] * wv_;
                acc2 += emb[24 + ii] * wv_;
            }
            float* hp = sm + HID2 + (trip * 64 + k) * 8;
            float h0 = silu_f(acc0), h1 = silu_f(acc1), h2 = silu_f(acc2);
            *(ull*)(hp + 0) = pack2(h0, h0);
            *(ull*)(hp + 2) = pack2(h1, h1);
            *(ull*)(hp + 4) = pack2(h2, h2);
        }
        __syncthreads();

        // ---- phase B: w = (hidden @ Wr2) * fcut, CTA-cooperative ----
        {
            const int p = tid >> 7;       // trip pair 0..3
            const int q = tid & 127;      // column pair 0..124
            if (q < 125) {
                const int col0 = q * 2;
                const bool full = (col0 < 100);   // edge-0 cols beyond 100 are dead
                const float* wbase = Wr2g + (size_t)l * 16000 + col0;
                const int t0 = p * 2, t1 = p * 2 + 1;
                const float* h0b = sm + HID2 + t0 * 512;
                const float* h1b = sm + HID2 + t1 * 512;
                ull a0 = 0, a1 = 0, a2 = 0, a3 = 0, a4 = 0, a5 = 0;
                #pragma unroll 4
                for (int j = 0; j < 64; j++) {
                    ull wv = __ldg((const ull*)(wbase + j * 250));
                    ulonglong2 hA = *(const ulonglong2*)(h0b + j * 8);
                    ull hA2      = *(const ull*)(h0b + j * 8 + 4);
                    ulonglong2 hB = *(const ulonglong2*)(h1b + j * 8);
                    ull hB2      = *(const ull*)(h1b + j * 8 + 4);
                    a1 = fma2(hA.y, wv, a1);
                    a2 = fma2(hA2,  wv, a2);
                    a4 = fma2(hB.y, wv, a4);
                    a5 = fma2(hB2,  wv, a5);
                    if (full) {
                        a0 = fma2(hA.x, wv, a0);
                        a3 = fma2(hB.x, wv, a3);
                    }
                }
                const ull* fcd = (const ull*)(sm + FCUTD);
                float* wall = sm + WALL;
                if (full) {
                    *(ull*)(wall + (t0 * 3 + 0) * 252 + col0) = mul2(a0, fcd[t0 * 3 + 0]);
                    *(ull*)(wall + (t1 * 3 + 0) * 252 + col0) = mul2(a3, fcd[t1 * 3 + 0]);
                }
                *(ull*)(wall + (t0 * 3 + 1) * 252 + col0) = mul2(a1, fcd[t0 * 3 + 1]);
                *(ull*)(wall + (t0 * 3 + 2) * 252 + col0) = mul2(a2, fcd[t0 * 3 + 2]);
                *(ull*)(wall + (t1 * 3 + 1) * 252 + col0) = mul2(a4, fcd[t1 * 3 + 1]);
                *(ull*)(wall + (t1 * 3 + 2) * 252 + col0) = mul2(a5, fcd[t1 * 3 + 2]);
            }
        }
        __syncthreads();

        // ---- phase M: messages, in-place state update ----
        if (k < CC) {
            const float* w0 = sm + WALL + (trip * 3 + 0) * 252;
            const float* w1 = sm + WALL + (trip * 3 + 1) * 252;
            const float* w2 = sm + WALL + (trip * 3 + 2) * 252;
            float4 s = *(const float4*)(ts + OF_S4 + k * 4);
            float* vcp = ts + OF_VC + k * 12;
            float v4x = vcp[0], v4y = vcp[1], v4z = vcp[2];
            float v3x = vcp[3], v3y = vcp[4], v3z = vcp[5];
            float v5x = vcp[6], v5y = vcp[7], v5z = vcp[8];
            float u0x = ts[OF_U + 0], u0y = ts[OF_U + 1];
            float u1x = ts[OF_U + 4], u1y = ts[OF_U + 5];
            float u2x = ts[OF_U + 8], u2y = ts[OF_U + 9];
            float s1 = s.x, s4v = s.y;

            // edge 1->4 (src v == 0 -> paths 0,1 only)
            float ms4  = w0[k] * s1;
            float w01  = w0[50 + k] * s1;
            float mv4x = w01 * u0x, mv4y = w01 * u0y;

            // edge 4->3
            float dot1 = v4x * u1x + v4y * u1y;
            float ms3  = w1[k] * s4v + w1[100 + k] * dot1;
            float cr1x = -v4z * u1y, cr1y = v4z * u1x, cr1z = v4x * u1y - v4y * u1x;
            const float* Ya = ts + OF_Y2 + 9;
            float y1x = v4x * Ya[0] + v4y * Ya[3] + v4z * Ya[6];
            float y1y = v4x * Ya[1] + v4y * Ya[4] + v4z * Ya[7];
            float y1z = v4x * Ya[2] + v4y * Ya[5] + v4z * Ya[8];
            float w11 = w1[50 + k] * s4v, w13 = w1[150 + k], w14 = w1[200 + k];
            float mv3x = w11 * u1x + w13 * cr1x + w14 * y1x;
            float mv3y = w11 * u1y + w13 * cr1y + w14 * y1y;
            float mv3z =             w13 * cr1z + w14 * y1z;

            // edge 4->5
            float dot2 = v4x * u2x + v4y * u2y;
            float ms5  = w2[k] * s4v + w2[100 + k] * dot2;
            float cr2x = -v4z * u2y, cr2y = v4z * u2x, cr2z = v4x * u2y - v4y * u2x;
            const float* Yb = ts + OF_Y2 + 18;
            float y2x = v4x * Yb[0] + v4y * Yb[3] + v4z * Yb[6];
            float y2y = v4x * Yb[1] + v4y * Yb[4] + v4z * Yb[7];
            float y2z = v4x * Yb[2] + v4y * Yb[5] + v4z * Yb[8];
            float w21 = w2[50 + k] * s4v, w23 = w2[150 + k], w24 = w2[200 + k];
            float mv5x = w21 * u2x + w23 * cr2x + w24 * y2x;
            float mv5y = w21 * u2y + w23 * cr2y + w24 * y2y;
            float mv5z =             w23 * cr2z + w24 * y2z;

            float h4 = s4v + ms4, h3 = s.z + ms3, h5 = s.w + ms5;
            *(float4*)(ts + OF_S4 + k * 4) = make_float4(s1, h4, h3, h5);
            *(float4*)(ts + OF_HG + k * 4) = make_float4(h4, h3, h5, 0.0f);
            *(float4*)(vcp + 0) = make_float4(v4x + mv4x, v4y + mv4y, v4z, v3x + mv3x);
            *(float4*)(vcp + 4) = make_float4(v3y + mv3y, v3z + mv3z, v5x + mv5x, v5y + mv5y);
            *(float4*)(vcp + 8) = make_float4(v5z + mv5z, 0.f, 0.f, 0.f);
        }
        __syncthreads();

        // ---- phase G: node GEMMs, f32x2 packed ----
        ull sacc0 = 0, sacc1 = 0, gacc0 = 0, gacc1 = 0;
        ull vA = 0, vB = 0, vCz = 0, vD = 0, vE = 0;
        if (k < CC) {
            const float* wssp = sm + WSS + k;
            const float* wgsp = sm + WGS + k;
            const float* wvsp = sm + WVS + k;
            const float* s4b = ts + OF_S4;
            const float* hgb = ts + OF_HG;
            const float* vcb = ts + OF_VC;
            #pragma unroll 2
            for (int c = 0; c < CC; c++) {
                float ws = wssp[c * 50], wg = wgsp[c * 50], wv = wvsp[c * 50];
                ull wsd = pack2(ws, ws), wgd = pack2(wg, wg), wvd = pack2(wv, wv);
                ulonglong2 sp = *(const ulonglong2*)(s4b + c * 4);
                ulonglong2 hp = *(const ulonglong2*)(hgb + c * 4);
                ulonglong2 va = *(const ulonglong2*)(vcb + c * 12);
                ulonglong2 vb = *(const ulonglong2*)(vcb + c * 12 + 4);
                ull vc2       = *(const ull*)(vcb + c * 12 + 8);
                sacc0 = fma2(sp.x, wsd, sacc0);
                sacc1 = fma2(sp.y, wsd, sacc1);
                gacc0 = fma2(hp.x, wgd, gacc0);
                gacc1 = fma2(hp.y, wgd, gacc1);
                vA = fma2(va.x, wvd, vA);
                vB = fma2(va.y, wvd, vB);
                vCz = fma2(vb.x, wvd, vCz);
                vD = fma2(vb.y, wvd, vD);
                vE = fma2(vc2, wvd, vE);
            }
        }
        __syncthreads();
        if (k < CC) {
            float s1p, s4p, s3p, s5p;
            unpack2(sacc0, s1p, s4p);
            unpack2(sacc1, s3p, s5p);
            *(float4*)(ts + OF_S4 + k * 4) =
                make_float4(silu_f(s1p), silu_f(s4p), silu_f(s3p), silu_f(s5p));
            float g4p, g3p, g5p, gxx;
            unpack2(gacc0, g4p, g3p);
            unpack2(gacc1, g5p, gxx);
            float g4 = sigm_f(g4p), g3 = sigm_f(g3p), g5 = sigm_f(g5p);
            float V4x, V4y, V4z, V3x, V3y, V3z, V5x, V5y, V5z, vxx;
            unpack2(vA, V4x, V4y);
            unpack2(vB, V4z, V3x);
            unpack2(vCz, V3y, V3z);
            unpack2(vD, V5x, V5y);
            unpack2(vE, V5z, vxx);
            float* vcp = ts + OF_VC + k * 12;
            *(float4*)(vcp + 0) = make_float4(V4x * g4, V4y * g4, V4z * g4, V3x * g3);
            *(float4*)(vcp + 4) = make_float4(V3y * g3, V3z * g3, V5x * g5, V5y * g5);
            *(float4*)(vcp + 8) = make_float4(V5z * g5, 0.f, 0.f, 0.f);
        }
    }
    __syncthreads();

    // ---------------- output ----------------
    if (k < 6) {
        int off = (k >> 1) * 3 + (k & 1);   // n4:{0,1} n3:{3,4} n5:{6,7}
        float acc = 0.0f;
        const float* vcb = ts + OF_VC;
        #pragma unroll 5
        for (int c = 0; c < CC; c++)
            acc += vcb[c * 12 + off] * __ldg(Woutg + c);
        ts[OF_OUTS + k] = acc;
    }
    __syncthreads();
    if (k == 0) {
        float o4x = ts[OF_OUTS + 0], o4y = ts[OF_OUTS + 1];
        float o3x = ts[OF_OUTS + 2], o3y = ts[OF_OUTS + 3];
        float o5x = ts[OF_OUTS + 4], o5y = ts[OF_OUTS + 5];
        float ox = ts[OF_OFF], oy = ts[OF_OFF + 1];
        float* dst = outp + ((size_t)(b * 514 + i + 1)) * 3;
        dst[0] = o3x + o4x + o5x;
        dst[1] = o3y + o4y + o5y;
        dst[2] = ox * (o3y - o5y) - oy * (o3x - o5x);
    }
}

extern "C" void kernel_launch(void* const* d_in, const int* in_sizes, int n_in,
                              void* d_out, int out_size) {
    const float* y    = (const float*)d_in[0];
    const float* Wemb = (const float*)d_in[1];
    const float* Wr1  = (const float*)d_in[2];
    const float* br1  = (const float*)d_in[3];
    const float* Wr2  = (const float*)d_in[4];
    const float* Ws   = (const float*)d_in[5];
    const float* Wv   = (const float*)d_in[6];
    const float* Wg   = (const float*)d_in[7];
    const float* Wo   = (const float*)d_in[8];
    float* outp = (float*)d_out;

    cudaMemsetAsync(outp, 0, (size_t)out_size * sizeof(float));

    cudaFuncSetAttribute(e3nn_kernel, cudaFuncAttributeMaxDynamicSharedMemorySize, SMEM_BYTES);
    e3nn_kernel<<<NBLK, NTHR, SMEM_BYTES>>>(y, Wemb, Wr1, br1, Wr2, Ws, Wv, Wg, Wo, outp);
}

// round 4
// speedup vs baseline: 1.5504x; 1.5504x over previous
#include <cuda_runtime.h>
#include <math.h>

#define NTHR 512
#define TRIPS 8
#define NBLK 4096
typedef unsigned long long ull;

// smem float offsets
#define WSS   0        // 50x50
#define WGS   2500
#define WVS   5000
#define HIDS  7500     // [8][64] ull pairs {h,h} (fcut folded)
#define WALLS 8524     // [8][104] edge-0 radial weights, cols 0..99
#define TST   9356
#define TSF   840
#define OF_H  0        // float4[50]: s/h for nodes (4,3,5,pad)
#define OF_VC 200      // [50][12]: v4xyz v3x | v3yz v5xy | v5z pad3
#define GEO   800      // [0..3]=u0x,u0y,u1x,u1y [4..15]=emb0 [16]=fc0 [17,18]=off [19..27]=Y2 [28..35]=scratch/outs
#define SMEM_FLOATS (TST + TRIPS * TSF)
#define SMEM_BYTES  (SMEM_FLOATS * 4)   // 64304

__device__ float g_s1[6][50];
__device__ float g_w1[6][256];

__device__ __forceinline__ float sigm_f(float x) { return 1.0f / (1.0f + __expf(-x)); }
__device__ __forceinline__ float silu_f(float x) { return x / (1.0f + __expf(-x)); }
__device__ __forceinline__ ull fma2(ull a, ull b, ull c) {
    ull d; asm("fma.rn.f32x2 %0, %1, %2, %3;" : "=l"(d) : "l"(a), "l"(b), "l"(c)); return d;
}
__device__ __forceinline__ ull pack2(float lo, float hi) {
    ull d; asm("mov.b64 %0, {%1, %2};" : "=l"(d) : "f"(lo), "f"(hi)); return d;
}
__device__ __forceinline__ void unpack2(ull v, float& lo, float& hi) {
    asm("mov.b64 {%0, %1}, %2;" : "=f"(lo), "=f"(hi) : "l"(v));
}

// Precompute: s1 trajectory (input-independent) and mirrored-edge radial
// weights w1 (r = 0.05 exactly for every triplet -> per-layer constant).
__global__ void setup_kernel(const float* __restrict__ We, const float* __restrict__ Wr1g,
                             const float* __restrict__ br1g, const float* __restrict__ Wr2g,
                             const float* __restrict__ Wsg) {
    __shared__ float hid[64];
    __shared__ float s[50];
    __shared__ float sn[50];
    int k = threadIdx.x;
    const float fc = 0.5f * (cosf(3.14159265358979f * (0.05f / 0.06f)) + 1.0f);
    if (k < 50) s[k] = We[k] + We[50 + k];
    for (int l = 0; l < 6; l++) {
        __syncthreads();
        if (k < 64) {
            float acc = br1g[l * 64 + k];
            #pragma unroll
            for (int ib = 0; ib < 10; ib++) {
                float z = 7.5f - (float)ib;        // (0.05*150 - ib)
                acc += __expf(-z * z) * fc * Wr1g[l * 768 + ib * 64 + k];
            }
            acc += Wr1g[l * 768 + 11 * 64 + k];    // edge_attr = (0,1)
            hid[k] = silu_f(acc);
        }
        if (k < 50) {
            g_s1[l][k] = s[k];
            float acc = 0.f;
            for (int c = 0; c < 50; c++) acc += s[c] * Wsg[l * 2500 + c * 50 + k];
            sn[k] = silu_f(acc);
        }
        __syncthreads();
        if (k < 50) s[k] = sn[k];
        if (k < 250) {
            float acc = 0.f;
            for (int j = 0; j < 64; j++) acc += hid[j] * Wr2g[l * 16000 + j * 250 + k];
            g_w1[l][k] = acc * fc;
        }
    }
}

__global__ void __launch_bounds__(NTHR, 2)
e3nn_kernel(const float* __restrict__ y, const float* __restrict__ Wemb,
            const float* __restrict__ Wr1g, const float* __restrict__ br1g,
            const float* __restrict__ Wr2g, const float* __restrict__ Wsg,
            const float* __restrict__ Wvg, const float* __restrict__ Wgg,
            const float* __restrict__ Woutg, float* __restrict__ outp)
{
    extern __shared__ float sm[];
    const int tid = threadIdx.x;
    const int trip = tid >> 6;
    const int k = tid & 63;
    float* ts = sm + TST + trip * TSF;
    float* g = ts + GEO;
    const int t = blockIdx.x * TRIPS + trip;
    const int b = t >> 9;
    const int i = t & 511;

    // ---- geometry ----
    if (k < 2) {
        const float* yy = y + (size_t)(b * 514 + i + k) * 6;
        float a = yy[2];
        float* bs = g + 28 + k * 4;
        bs[0] = yy[0]; bs[1] = yy[1];
        bs[2] = -0.05f * sinf(a); bs[3] = 0.05f * cosf(a);
    }
    __syncthreads();
    if (k == 0) {
        float vx = g[28] - g[32], vy = g[29] - g[33];   // ctr0 - ctr1 (edge 1->4)
        float r = sqrtf(vx * vx + vy * vy);
        float inv = 1.0f / (r + 1e-12f);
        g[0] = vx * inv; g[1] = vy * inv;
        float ox = g[34], oy = g[35];                   // off1
        g[2] = -ox * 20.f; g[3] = -oy * 20.f;           // u1 = -off/0.05
        float tt = fminf(r * (1.0f / 0.06f), 1.0f);
        float fc = 0.5f * (cosf(3.14159265358979f * tt) + 1.0f);
        g[16] = fc;
        #pragma unroll
        for (int ib = 0; ib < 10; ib++) {
            float z = r * 150.f - (float)ib;
            g[4 + ib] = __expf(-z * z) * fc;
        }
        g[14] = 1.f; g[15] = 0.f;                       // edge-0 attr
        g[17] = ox; g[18] = oy;
        float u3[3] = {g[2], g[3], 0.f};
        #pragma unroll
        for (int rr = 0; rr < 3; rr++)
            #pragma unroll
            for (int cc = 0; cc < 3; cc++)
                g[19 + rr * 3 + cc] = u3[rr] * u3[cc] - (rr == cc ? (1.f / 3.f) : 0.f);
    }
    if (k < 50) {
        float e0 = Wemb[k], e1 = Wemb[50 + k], e2 = Wemb[100 + k];
        *(float4*)(ts + OF_H + k * 4) = make_float4(e0 + e1, e0 + e2, e0 + e2, 0.f);
        float4 z4 = make_float4(0.f, 0.f, 0.f, 0.f);
        *(float4*)(ts + OF_VC + k * 12 + 0) = z4;
        *(float4*)(ts + OF_VC + k * 12 + 4) = z4;
        *(float4*)(ts + OF_VC + k * 12 + 8) = z4;
    }

    // ---- layers ----
    for (int l = 0; l < 6; l++) {
        __syncthreads();
        {   // stage node weights
            const float4* a4 = (const float4*)(Wsg + (size_t)l * 2500);
            const float4* b4 = (const float4*)(Wgg + (size_t)l * 2500);
            const float4* c4 = (const float4*)(Wvg + (size_t)l * 2500);
            for (int idx = tid; idx < 625; idx += NTHR) {
                ((float4*)(sm + WSS))[idx] = a4[idx];
                ((float4*)(sm + WGS))[idx] = b4[idx];
                ((float4*)(sm + WVS))[idx] = c4[idx];
            }
        }
        // phase A: edge-0 hidden (fcut folded in)
        {
            float acc = __ldg(br1g + l * 64 + k);
            const float* wr1 = Wr1g + l * 768 + k;
            #pragma unroll
            for (int ii = 0; ii < 12; ii++) acc += g[4 + ii] * __ldg(wr1 + ii * 64);
            float h = silu_f(acc) * g[16];
            ((ull*)(sm + HIDS))[trip * 64 + k] = pack2(h, h);
        }
        __syncthreads();
        // phase B: edge-0 radial weights, cols 0..99 only
        if (k < 50) {
            const float* wb = Wr2g + (size_t)l * 16000 + 2 * k;
            const ull* hp = (const ull*)(sm + HIDS) + trip * 64;
            ull acc = 0;
            #pragma unroll 8
            for (int j = 0; j < 64; j++)
                acc = fma2(hp[j], __ldg((const ull*)(wb + (size_t)j * 250)), acc);
            *(ull*)(sm + WALLS + trip * 104 + 2 * k) = acc;
        }
        __syncthreads();
        // phase M: messages + state update
        if (k < 50) {
            float w0a = sm[WALLS + trip * 104 + k];
            float w0b = sm[WALLS + trip * 104 + 50 + k];
            const float* w1p = g_w1[l];
            float w1a = __ldg(w1p + k),       w1b = __ldg(w1p + 50 + k);
            float w1c = __ldg(w1p + 100 + k), w1d = __ldg(w1p + 150 + k), w1e = __ldg(w1p + 200 + k);
            float s1v = __ldg(&g_s1[l][k]);
            float4 hc = *(const float4*)(ts + OF_H + k * 4);
            float s4 = hc.x, s3 = hc.y, s5 = hc.z;
            float* vcp = ts + OF_VC + k * 12;
            float4 va = *(const float4*)(vcp);
            float4 vb = *(const float4*)(vcp + 4);
            float v5z = vcp[8];
            float v4x = va.x, v4y = va.y, v4z = va.z, v3x = va.w;
            float v3y = vb.x, v3z = vb.y, v5x = vb.z, v5y = vb.w;
            float u0x = g[0], u0y = g[1], u1x = g[2], u1y = g[3];

            float ms4 = w0a * s1v, w01 = w0b * s1v;
            float mv4x = w01 * u0x, mv4y = w01 * u0y;

            float base = w1a * s4, a_ = w1b * s4;
            float dot = v4x * u1x + v4y * u1y;
            float wd = w1c * dot;
            float crx = -v4z * u1y, cry = v4z * u1x, crz = v4x * u1y - v4y * u1x;
            const float* Y = g + 19;
            float yx  = v4x * Y[0] + v4y * Y[3] + v4z * Y[6];
            float yy2 = v4x * Y[1] + v4y * Y[4] + v4z * Y[7];
            float yz  = v4x * Y[2] + v4y * Y[5] + v4z * Y[8];
            float axu = a_ * u1x, ayu = a_ * u1y;
            float bx = w1d * crx, by = w1d * cry, bz = w1d * crz;
            float cx2 = w1e * yx, cy2 = w1e * yy2, cz2 = w1e * yz;

            *(float4*)(ts + OF_H + k * 4) = make_float4(s4 + ms4, s3 + base + wd, s5 + base - wd, 0.f);
            *(float4*)(vcp)     = make_float4(v4x + mv4x, v4y + mv4y, v4z, v3x + axu + bx + cx2);
            *(float4*)(vcp + 4) = make_float4(v3y + ayu + by + cy2, v3z + bz + cz2,
                                              v5x - axu - bx + cx2, v5y - ayu - by + cy2);
            vcp[8] = v5z - bz + cz2;
        }
        __syncthreads();
        // phase G: node GEMMs (Ws, Wg, Wv), f32x2
        ull sa0 = 0, sa1 = 0, ga0 = 0, ga1 = 0, vA = 0, vB = 0, vC = 0, vD = 0, vE = 0;
        if (k < 50) {
            const float* wsp = sm + WSS + k;
            const float* wgp = sm + WGS + k;
            const float* wvp = sm + WVS + k;
            const float* hb = ts + OF_H;
            const float* vcb = ts + OF_VC;
            #pragma unroll 2
            for (int c = 0; c < 50; c++) {
                float ws = wsp[c * 50], wg = wgp[c * 50], wv = wvp[c * 50];
                ull wsd = pack2(ws, ws), wgd = pack2(wg, wg), wvd = pack2(wv, wv);
                ulonglong2 hp = *(const ulonglong2*)(hb + c * 4);
                ulonglong2 p = *(const ulonglong2*)(vcb + c * 12);
                ulonglong2 q = *(const ulonglong2*)(vcb + c * 12 + 4);
                ull r2 = *(const ull*)(vcb + c * 12 + 8);
                sa0 = fma2(hp.x, wsd, sa0); sa1 = fma2(hp.y, wsd, sa1);
                ga0 = fma2(hp.x, wgd, ga0); ga1 = fma2(hp.y, wgd, ga1);
                vA = fma2(p.x, wvd, vA); vB = fma2(p.y, wvd, vB);
                vC = fma2(q.x, wvd, vC); vD = fma2(q.y, wvd, vD);
                vE = fma2(r2, wvd, vE);
            }
        }
        __syncthreads();
        if (k < 50) {
            float s4p, s3p, s5p, xx;
            unpack2(sa0, s4p, s3p); unpack2(sa1, s5p, xx);
            *(float4*)(ts + OF_H + k * 4) = make_float4(silu_f(s4p), silu_f(s3p), silu_f(s5p), 0.f);
            float g4r, g3r, g5r;
            unpack2(ga0, g4r, g3r); unpack2(ga1, g5r, xx);
            float g4 = sigm_f(g4r), g3 = sigm_f(g3r), g5 = sigm_f(g5r);
            float V4x, V4y, V4z, V3x, V3y, V3z, V5x, V5y, V5z;
            unpack2(vA, V4x, V4y); unpack2(vB, V4z, V3x); unpack2(vC, V3y, V3z);
            unpack2(vD, V5x, V5y); unpack2(vE, V5z, xx);
            float* vcp = ts + OF_VC + k * 12;
            *(float4*)(vcp)     = make_float4(V4x * g4, V4y * g4, V4z * g4, V3x * g3);
            *(float4*)(vcp + 4) = make_float4(V3y * g3, V3z * g3, V5x * g5, V5y * g5);
            vcp[8] = V5z * g5;
        }
    }
    __syncthreads();

    // ---- epilogue ----
    if (k < 6) {
        int off = (k >> 1) * 3 + (k & 1);   // n4{0,1} n3{3,4} n5{6,7}
        float acc = 0.f;
        #pragma unroll 5
        for (int c = 0; c < 50; c++) acc += ts[OF_VC + c * 12 + off] * __ldg(Woutg + c);
        g[28 + k] = acc;
    }
    __syncthreads();
    if (k == 0) {
        float o4x = g[28], o4y = g[29], o3x = g[30], o3y = g[31], o5x = g[32], o5y = g[33];
        float ox = g[17], oy = g[18];
        float* dst = outp + (size_t)(b * 514 + i + 1) * 3;
        dst[0] = o3x + o4x + o5x;
        dst[1] = o3y + o4y + o5y;
        dst[2] = ox * (o3y - o5y) - oy * (o3x - o5x);
    }
}

extern "C" void kernel_launch(void* const* d_in, const int* in_sizes, int n_in,
                              void* d_out, int out_size) {
    const float* y    = (const float*)d_in[0];
    const float* Wemb = (const float*)d_in[1];
    const float* Wr1  = (const float*)d_in[2];
    const float* br1  = (const float*)d_in[3];
    const float* Wr2  = (const float*)d_in[4];
    const float* Ws   = (const float*)d_in[5];
    const float* Wv   = (const float*)d_in[6];
    const float* Wg   = (const float*)d_in[7];
    const float* Wo   = (const float*)d_in[8];
    float* outp = (float*)d_out;

    cudaMemsetAsync(outp, 0, (size_t)out_size * sizeof(float));
    setup_kernel<<<1, 256>>>(Wemb, Wr1, br1, Wr2, Ws);
    cudaFuncSetAttribute(e3nn_kernel, cudaFuncAttributeMaxDynamicSharedMemorySize, SMEM_BYTES);
    e3nn_kernel<<<NBLK, NTHR, SMEM_BYTES>>>(y, Wemb, Wr1, br1, Wr2, Ws, Wv, Wg, Wo, outp);
}